// round 1
// baseline (speedup 1.0000x reference)
#include <cuda_runtime.h>
#include <math_constants.h>

// Problem constants
#define NB      32
#define DIM     64
#define HW      4096            // 64*64
#define N_ROWS  (NB * HW)       // 131072
#define N_CODES 1024
#define N_ELEMS (N_ROWS * DIM)  // 8388608

#define TILE_C  128
#define N_TILES (N_CODES / TILE_C)

#define K2_BLOCKS  2048
#define K2_THREADS 1024
// each K2 thread handles 4 consecutive elements (float4): 2048*1024*4 = 8388608

// Device scratch (no allocations allowed)
__device__ int    g_best_idx[N_ROWS];
__device__ double g_partials[K2_BLOCKS];

// ---------------------------------------------------------------------------
// Kernel 1: per-row argmin over 1024 codes.
// Replicates reference fp32 rounding:  score_c = RN( RN(s1 + s2_c) - 2*cross_c )
// Tie-break: first (lowest) index, via strict < in ascending c.
// ---------------------------------------------------------------------------
__global__ void __launch_bounds__(256)
vq_argmin_kernel(const float* __restrict__ z, const float* __restrict__ cb)
{
    __shared__ float s_cb[TILE_C][DIM];   // 32 KB
    __shared__ float s_s2[TILE_C];

    const int tid = threadIdx.x;
    const int row = blockIdx.x * 256 + tid;   // 512 blocks * 256 = 131072
    const int b   = row >> 12;                // row / 4096
    const int hw  = row & 4095;

    // Load z row: z[b][k][h][w], stride HW between channels. Coalesced across
    // threads (consecutive hw).
    const float* zp = z + (size_t)b * (DIM * HW) + hw;
    float zr[DIM];
    double s1d = 0.0;
    #pragma unroll
    for (int k = 0; k < DIM; k++) {
        float v = zp[(size_t)k * HW];
        zr[k] = v;
        float sq = __fmul_rn(v, v);       // fp32 square first (matches ref z**2)
        s1d += (double)sq;                // correctly-rounded sum -> same binade
    }
    const float s1 = (float)s1d;

    float best = CUDART_INF_F;
    int   bidx = 0;

    for (int t = 0; t < N_TILES; t++) {
        __syncthreads();
        // Cooperative tile load: 128 codes * 64 floats = 2048 float4
        const float4* src = (const float4*)(cb + (size_t)t * TILE_C * DIM);
        float4* dst = (float4*)&s_cb[0][0];
        #pragma unroll
        for (int i = 0; i < 8; i++) {
            dst[tid + i * 256] = src[tid + i * 256];
        }
        __syncthreads();
        if (tid < TILE_C) {
            float acc = 0.0f;
            #pragma unroll
            for (int k = 0; k < DIM; k++)
                acc = __fadd_rn(acc, __fmul_rn(s_cb[tid][k], s_cb[tid][k]));
            s_s2[tid] = acc;
        }
        __syncthreads();

        #pragma unroll 4
        for (int c = 0; c < TILE_C; c++) {
            const float4* ep = (const float4*)s_cb[c];   // broadcast reads
            float a0 = 0.f, a1 = 0.f, a2 = 0.f, a3 = 0.f;
            #pragma unroll
            for (int k = 0; k < DIM / 4; k++) {
                float4 e = ep[k];
                a0 = fmaf(zr[4 * k + 0], e.x, a0);
                a1 = fmaf(zr[4 * k + 1], e.y, a1);
                a2 = fmaf(zr[4 * k + 2], e.z, a2);
                a3 = fmaf(zr[4 * k + 3], e.w, a3);
            }
            float cross = __fadd_rn(__fadd_rn(a0, a1), __fadd_rn(a2, a3));
            // Exact reference rounding chain: t = RN(s1 + s2); d = RN(t - 2*cross)
            float tt    = __fadd_rn(s1, s_s2[c]);
            float score = __fadd_rn(tt, -__fmul_rn(2.0f, cross));
            if (score < best) { best = score; bidx = t * TILE_C + c; }
        }
    }
    g_best_idx[row] = bidx;
}

// ---------------------------------------------------------------------------
// Kernel 2: gather + straight-through output + fp64 partial sums of (z_q - z)^2
// out = RN( z + RN(z_q - z) )   -- exact reference elementwise chain
// ---------------------------------------------------------------------------
__global__ void __launch_bounds__(K2_THREADS)
vq_apply_kernel(const float* __restrict__ z, const float* __restrict__ cb,
                float* __restrict__ out)
{
    __shared__ double s_red[K2_THREADS];

    const int tid = threadIdx.x;
    const int n0  = (blockIdx.x * K2_THREADS + tid) * 4;   // first element

    const int b = n0 >> 18;
    const int c = (n0 >> 12) & 63;
    const int h = (n0 >> 6) & 63;
    const int w = n0 & 63;            // w, w+1, w+2, w+3 stay within the row
    const int row0 = b * HW + h * 64 + w;

    float4 zv = *(const float4*)(z + n0);

    int i0 = g_best_idx[row0 + 0];
    int i1 = g_best_idx[row0 + 1];
    int i2 = g_best_idx[row0 + 2];
    int i3 = g_best_idx[row0 + 3];

    float q0 = cb[i0 * DIM + c];
    float q1 = cb[i1 * DIM + c];
    float q2 = cb[i2 * DIM + c];
    float q3 = cb[i3 * DIM + c];

    float d0 = __fadd_rn(q0, -zv.x);
    float d1 = __fadd_rn(q1, -zv.y);
    float d2 = __fadd_rn(q2, -zv.z);
    float d3 = __fadd_rn(q3, -zv.w);

    float4 ov;
    ov.x = __fadd_rn(zv.x, d0);
    ov.y = __fadd_rn(zv.y, d1);
    ov.z = __fadd_rn(zv.z, d2);
    ov.w = __fadd_rn(zv.w, d3);
    *(float4*)(out + n0) = ov;

    double acc = (double)__fmul_rn(d0, d0) + (double)__fmul_rn(d1, d1)
               + (double)__fmul_rn(d2, d2) + (double)__fmul_rn(d3, d3);

    // deterministic block tree reduction
    s_red[tid] = acc;
    __syncthreads();
    for (int s = K2_THREADS / 2; s > 0; s >>= 1) {
        if (tid < s) s_red[tid] += s_red[tid + s];
        __syncthreads();
    }
    if (tid == 0) g_partials[blockIdx.x] = s_red[0];
}

// ---------------------------------------------------------------------------
// Kernel 3: deterministic final reduction + loss
// vq_loss = m + 0.25*m  where m = mean((z_q - z)^2)
// ---------------------------------------------------------------------------
__global__ void __launch_bounds__(1024)
vq_loss_kernel(float* __restrict__ out, long long loss_pos)
{
    __shared__ double s_buf[K2_BLOCKS];
    const int tid = threadIdx.x;
    #pragma unroll
    for (int i = 0; i < K2_BLOCKS / 1024; i++)
        s_buf[tid + i * 1024] = g_partials[tid + i * 1024];
    __syncthreads();
    if (tid == 0) {
        double s = 0.0;
        for (int i = 0; i < K2_BLOCKS; i++) s += s_buf[i];   // fixed order
        float m = (float)(s * (1.0 / (double)N_ELEMS));
        float v = __fadd_rn(m, __fmul_rn(0.25f, m));
        out[loss_pos] = v;
    }
}

// ---------------------------------------------------------------------------
extern "C" void kernel_launch(void* const* d_in, const int* in_sizes, int n_in,
                              void* d_out, int out_size)
{
    const float* z  = (const float*)d_in[0];   // [32, 64, 64, 64] fp32
    const float* cb = (const float*)d_in[1];   // [1024, 64] fp32
    float* out = (float*)d_out;                // [8388608 z_q_st] + [1 loss]

    vq_argmin_kernel<<<N_ROWS / 256, 256>>>(z, cb);
    vq_apply_kernel<<<K2_BLOCKS, K2_THREADS>>>(z, cb, out);

    long long loss_pos = (long long)out_size - 1;
    if (loss_pos < N_ELEMS) loss_pos = N_ELEMS;  // defensive; expect out_size = 8388609
    vq_loss_kernel<<<1, 1024>>>(out, loss_pos);
}

// round 5
// speedup vs baseline: 1.3285x; 1.3285x over previous
#include <cuda_runtime.h>
#include <math_constants.h>

// Problem constants
#define NB      32
#define DIM     64
#define HW      4096            // 64*64
#define N_ROWS  (NB * HW)       // 131072
#define N_CODES 1024
#define N_ELEMS (N_ROWS * DIM)  // 8388608

#define TILE_C  128
#define N_TILES (N_CODES / TILE_C)

#define K2_BLOCKS  512
#define K2_THREADS 1024
// each K2 thread handles 16 consecutive elements: 512*1024*16 = 8388608

// Device scratch (no allocations allowed)
__device__ int    g_best_idx[N_ROWS];
__device__ double g_partials[K2_BLOCKS];

// ---- packed fp32x2 helpers (sm_100+) ---------------------------------------
__device__ __forceinline__ void fma2(unsigned long long& d,
                                     unsigned long long a,
                                     unsigned long long b) {
    asm("fma.rn.f32x2 %0, %1, %2, %0;" : "+l"(d) : "l"(a), "l"(b));
}
__device__ __forceinline__ unsigned long long add2(unsigned long long a,
                                                   unsigned long long b) {
    unsigned long long r;
    asm("add.rn.f32x2 %0, %1, %2;" : "=l"(r) : "l"(a), "l"(b));
    return r;
}
__device__ __forceinline__ unsigned long long pack2(float lo, float hi) {
    unsigned long long r;
    asm("mov.b64 %0, {%1, %2};" : "=l"(r) : "f"(lo), "f"(hi));
    return r;
}
__device__ __forceinline__ void unpack2(unsigned long long p, float& lo, float& hi) {
    asm("mov.b64 {%0, %1}, %2;" : "=f"(lo), "=f"(hi) : "l"(p));
}

// ---------------------------------------------------------------------------
// Kernel 1: per-row argmin over 1024 codes.
// Replicates reference fp32 rounding:  score_c = RN( RN(s1 + s2_c) - 2*cross_c )
// (fmaf(-2,cross,tt) == RN(tt - 2*cross) exactly, since 2*cross is exact.)
// Tie-break: first (lowest) index, via strict < in ascending c.
// FIX vs R2/R4: inner j-loop covers all 16 ulonglong2 (256 B = 64 dims),
// not 8 (which silently dropped half the vector and broke every score).
// ---------------------------------------------------------------------------
__global__ void __launch_bounds__(256)
vq_argmin_kernel(const float* __restrict__ z, const float* __restrict__ cb)
{
    __shared__ float s_cb[TILE_C][DIM];   // 32 KB
    __shared__ float s_s2[TILE_C];

    const int tid = threadIdx.x;
    const int row = blockIdx.x * 256 + tid;   // 512 blocks * 256 = 131072
    const int b   = row >> 12;                // row / 4096
    const int hw  = row & 4095;

    // Load z row: z[b][k][h][w], stride HW between channels. Coalesced across
    // threads (consecutive hw). Pack pairs along k for f32x2 math.
    const float* zp = z + (size_t)b * (DIM * HW) + hw;
    unsigned long long zr2[DIM / 2];
    double s1d = 0.0;
    #pragma unroll
    for (int k = 0; k < DIM / 2; k++) {
        float v0 = zp[(size_t)(2 * k)     * HW];
        float v1 = zp[(size_t)(2 * k + 1) * HW];
        s1d += (double)__fmul_rn(v0, v0);     // same order as R1 (which matched)
        s1d += (double)__fmul_rn(v1, v1);
        zr2[k] = pack2(v0, v1);
    }
    const float s1 = (float)s1d;

    float best = CUDART_INF_F;
    int   bidx = 0;

    for (int t = 0; t < N_TILES; t++) {
        __syncthreads();
        // Cooperative tile load: 128 codes * 64 floats = 2048 float4
        const float4* src = (const float4*)(cb + (size_t)t * TILE_C * DIM);
        float4* dst = (float4*)&s_cb[0][0];
        #pragma unroll
        for (int i = 0; i < 8; i++) {
            dst[tid + i * 256] = src[tid + i * 256];
        }
        __syncthreads();
        if (tid < TILE_C) {
            float acc = 0.0f;
            #pragma unroll
            for (int k = 0; k < DIM; k++)
                acc = __fadd_rn(acc, __fmul_rn(s_cb[tid][k], s_cb[tid][k]));
            s_s2[tid] = acc;
        }
        __syncthreads();

        #pragma unroll 4
        for (int c = 0; c < TILE_C; c++) {
            // Broadcast LDS.128: each ulonglong2 carries two packed f32x2
            // operands (floats 4j..4j+3 of the code row). 16 loads = 64 dims.
            const ulonglong2* ep = (const ulonglong2*)s_cb[c];
            unsigned long long a0 = 0ull, a1 = 0ull, a2 = 0ull, a3 = 0ull;
            #pragma unroll
            for (int j = 0; j < 16; j++) {
                ulonglong2 e = ep[j];
                if ((j & 1) == 0) {
                    fma2(a0, zr2[2 * j],     e.x);
                    fma2(a1, zr2[2 * j + 1], e.y);
                } else {
                    fma2(a2, zr2[2 * j],     e.x);
                    fma2(a3, zr2[2 * j + 1], e.y);
                }
            }
            unsigned long long s01 = add2(a0, a1);
            unsigned long long s23 = add2(a2, a3);
            unsigned long long sA  = add2(s01, s23);
            float lo, hi;
            unpack2(sA, lo, hi);
            float cross = __fadd_rn(lo, hi);
            float tt    = __fadd_rn(s1, s_s2[c]);
            float score = __fmaf_rn(-2.0f, cross, tt);   // == RN(tt - 2*cross)
            if (score < best) { best = score; bidx = t * TILE_C + c; }
        }
    }
    g_best_idx[row] = bidx;
}

// ---------------------------------------------------------------------------
// Kernel 2: gather + straight-through output + fp64 partial sums of (z_q - z)^2
// out = RN( z + RN(z_q - z) )   -- exact reference elementwise chain
// 16 consecutive elements per thread; shfl-based deterministic reduction.
// ---------------------------------------------------------------------------
__global__ void __launch_bounds__(K2_THREADS)
vq_apply_kernel(const float* __restrict__ z, const float* __restrict__ cb,
                float* __restrict__ out)
{
    __shared__ double s_warp[K2_THREADS / 32];

    const int tid  = threadIdx.x;
    const int lane = tid & 31;
    const int wid  = tid >> 5;
    const long long base = ((long long)blockIdx.x * K2_THREADS + tid) * 16;

    const int b   = (int)(base >> 18);
    const int cch = (int)(base >> 12) & 63;
    const int h   = (int)(base >> 6) & 63;
    const int w   = (int)base & 63;          // multiple of 16; stays in row
    const int row0 = b * HW + h * 64 + w;

    double acc = 0.0;
    #pragma unroll
    for (int g = 0; g < 4; g++) {
        float4 zv = *(const float4*)(z + base + 4 * g);
        int4   iv = *(const int4*)(g_best_idx + row0 + 4 * g);

        float q0 = cb[iv.x * DIM + cch];
        float q1 = cb[iv.y * DIM + cch];
        float q2 = cb[iv.z * DIM + cch];
        float q3 = cb[iv.w * DIM + cch];

        float d0 = __fadd_rn(q0, -zv.x);
        float d1 = __fadd_rn(q1, -zv.y);
        float d2 = __fadd_rn(q2, -zv.z);
        float d3 = __fadd_rn(q3, -zv.w);

        float4 ov;
        ov.x = __fadd_rn(zv.x, d0);
        ov.y = __fadd_rn(zv.y, d1);
        ov.z = __fadd_rn(zv.z, d2);
        ov.w = __fadd_rn(zv.w, d3);
        *(float4*)(out + base + 4 * g) = ov;

        float sg = __fadd_rn(__fadd_rn(__fmul_rn(d0, d0), __fmul_rn(d1, d1)),
                             __fadd_rn(__fmul_rn(d2, d2), __fmul_rn(d3, d3)));
        acc += (double)sg;
    }

    // deterministic warp reduction (fixed shuffle order)
    #pragma unroll
    for (int off = 16; off > 0; off >>= 1)
        acc += __shfl_down_sync(0xffffffffu, acc, off);
    if (lane == 0) s_warp[wid] = acc;
    __syncthreads();
    if (wid == 0) {
        double v = s_warp[lane];
        #pragma unroll
        for (int off = 16; off > 0; off >>= 1)
            v += __shfl_down_sync(0xffffffffu, v, off);
        if (lane == 0) g_partials[blockIdx.x] = v;
    }
}

// ---------------------------------------------------------------------------
// Kernel 3: deterministic final reduction + loss
// vq_loss = m + 0.25*m  where m = mean((z_q - z)^2)
// ---------------------------------------------------------------------------
__global__ void __launch_bounds__(K2_BLOCKS)
vq_loss_kernel(float* __restrict__ out, long long loss_pos)
{
    __shared__ double s_buf[K2_BLOCKS];
    const int tid = threadIdx.x;
    s_buf[tid] = g_partials[tid];
    __syncthreads();
    #pragma unroll
    for (int s = K2_BLOCKS / 2; s > 0; s >>= 1) {
        if (tid < s) s_buf[tid] += s_buf[tid + s];
        __syncthreads();
    }
    if (tid == 0) {
        float m = (float)(s_buf[0] * (1.0 / (double)N_ELEMS));
        float v = __fadd_rn(m, __fmul_rn(0.25f, m));
        out[loss_pos] = v;
    }
}

// ---------------------------------------------------------------------------
extern "C" void kernel_launch(void* const* d_in, const int* in_sizes, int n_in,
                              void* d_out, int out_size)
{
    const float* z  = (const float*)d_in[0];   // [32, 64, 64, 64] fp32
    const float* cb = (const float*)d_in[1];   // [1024, 64] fp32
    float* out = (float*)d_out;                // [8388608 z_q_st] + [1 loss]

    vq_argmin_kernel<<<N_ROWS / 256, 256>>>(z, cb);
    vq_apply_kernel<<<K2_BLOCKS, K2_THREADS>>>(z, cb, out);

    long long loss_pos = (long long)out_size - 1;
    if (loss_pos < N_ELEMS) loss_pos = N_ELEMS;  // defensive; expect 8388609
    vq_loss_kernel<<<1, K2_BLOCKS>>>(out, loss_pos);
}

// round 6
// speedup vs baseline: 1.3418x; 1.0101x over previous
#include <cuda_runtime.h>
#include <math_constants.h>

// Problem constants
#define NB      32
#define DIM     64
#define HW      4096            // 64*64
#define N_ROWS  (NB * HW)       // 131072
#define N_CODES 1024
#define N_ELEMS (N_ROWS * DIM)  // 8388608

#define TILE_C  128
#define N_TILES (N_CODES / TILE_C)

#define K2_BLOCKS  512
#define K2_THREADS 1024
// each K2 thread handles 16 consecutive elements: 512*1024*16 = 8388608

// Device scratch (no allocations allowed)
__device__ int    g_best_idx[N_ROWS];
__device__ double g_partials[K2_BLOCKS];

// ---- packed fp32x2 helpers (sm_100+) ---------------------------------------
__device__ __forceinline__ void fma2(unsigned long long& d,
                                     unsigned long long a,
                                     unsigned long long b) {
    asm("fma.rn.f32x2 %0, %1, %2, %0;" : "+l"(d) : "l"(a), "l"(b));
}
__device__ __forceinline__ unsigned long long add2(unsigned long long a,
                                                   unsigned long long b) {
    unsigned long long r;
    asm("add.rn.f32x2 %0, %1, %2;" : "=l"(r) : "l"(a), "l"(b));
    return r;
}
__device__ __forceinline__ unsigned long long pack2(float lo, float hi) {
    unsigned long long r;
    asm("mov.b64 %0, {%1, %2};" : "=l"(r) : "f"(lo), "f"(hi));
    return r;
}
__device__ __forceinline__ void unpack2(unsigned long long p, float& lo, float& hi) {
    asm("mov.b64 {%0, %1}, %2;" : "=f"(lo), "=f"(hi) : "l"(p));
}

// ---------------------------------------------------------------------------
// Kernel 1: per-row argmin over 1024 codes, TWO rows per thread.
// Each LDS.128 of a code operand feeds both rows (4 FFMA2), halving total
// smem wavefronts vs R5 (the pipe ncu showed at 79%).
// Score chain per row is IDENTICAL to R5 (which had rel_err = 0):
//   score_c = fmaf(-2, cross, RN(s1 + s2_c)),  cross grouped a0..a3 by j parity.
// Tie-break: strict < in ascending c.
// ---------------------------------------------------------------------------
__global__ void __launch_bounds__(256)
vq_argmin_kernel(const float* __restrict__ z, const float* __restrict__ cb)
{
    __shared__ float s_cb[TILE_C][DIM];   // 32 KB
    __shared__ float s_s2[TILE_C];

    const int tid  = threadIdx.x;
    const int rowA = blockIdx.x * 256 + tid;      // 0 .. 65535   (b in 0..15)
    const int rowB = rowA + (N_ROWS / 2);         // 65536..131071 (b in 16..31)

    // Load both z rows. z[b][k][h][w], channel stride HW; coalesced across
    // threads (consecutive hw). Pack k-pairs for f32x2 math.
    const int bA = rowA >> 12, hwA = rowA & 4095;
    const int bB = rowB >> 12, hwB = rowB & 4095;
    const float* zpA = z + (size_t)bA * (DIM * HW) + hwA;
    const float* zpB = z + (size_t)bB * (DIM * HW) + hwB;

    unsigned long long zA[DIM / 2], zB[DIM / 2];
    double s1dA = 0.0, s1dB = 0.0;
    #pragma unroll
    for (int k = 0; k < DIM / 2; k++) {
        float a0 = zpA[(size_t)(2 * k)     * HW];
        float a1 = zpA[(size_t)(2 * k + 1) * HW];
        s1dA += (double)__fmul_rn(a0, a0);
        s1dA += (double)__fmul_rn(a1, a1);
        zA[k] = pack2(a0, a1);
        float b0 = zpB[(size_t)(2 * k)     * HW];
        float b1 = zpB[(size_t)(2 * k + 1) * HW];
        s1dB += (double)__fmul_rn(b0, b0);
        s1dB += (double)__fmul_rn(b1, b1);
        zB[k] = pack2(b0, b1);
    }
    const float s1A = (float)s1dA;
    const float s1B = (float)s1dB;

    float bestA = CUDART_INF_F, bestB = CUDART_INF_F;
    int   idxA = 0, idxB = 0;

    for (int t = 0; t < N_TILES; t++) {
        __syncthreads();
        // Cooperative tile load: 128 codes * 64 floats = 2048 float4
        const float4* src = (const float4*)(cb + (size_t)t * TILE_C * DIM);
        float4* dst = (float4*)&s_cb[0][0];
        #pragma unroll
        for (int i = 0; i < 8; i++) {
            dst[tid + i * 256] = src[tid + i * 256];
        }
        __syncthreads();
        if (tid < TILE_C) {
            float acc = 0.0f;
            #pragma unroll
            for (int k = 0; k < DIM; k++)
                acc = __fadd_rn(acc, __fmul_rn(s_cb[tid][k], s_cb[tid][k]));
            s_s2[tid] = acc;
        }
        __syncthreads();

        #pragma unroll 2
        for (int c = 0; c < TILE_C; c++) {
            // Broadcast LDS.128: ep[j] = code floats [4j..4j+3]; 16 loads = 64 dims.
            const ulonglong2* ep = (const ulonglong2*)s_cb[c];
            unsigned long long A0 = 0ull, A1 = 0ull, A2 = 0ull, A3 = 0ull;
            unsigned long long B0 = 0ull, B1 = 0ull, B2 = 0ull, B3 = 0ull;
            #pragma unroll
            for (int j = 0; j < 16; j++) {
                ulonglong2 e = ep[j];
                if ((j & 1) == 0) {
                    fma2(A0, zA[2 * j],     e.x);
                    fma2(A1, zA[2 * j + 1], e.y);
                    fma2(B0, zB[2 * j],     e.x);
                    fma2(B1, zB[2 * j + 1], e.y);
                } else {
                    fma2(A2, zA[2 * j],     e.x);
                    fma2(A3, zA[2 * j + 1], e.y);
                    fma2(B2, zB[2 * j],     e.x);
                    fma2(B3, zB[2 * j + 1], e.y);
                }
            }
            const float s2c = s_s2[c];

            unsigned long long sa = add2(add2(A0, A1), add2(A2, A3));
            float loA, hiA; unpack2(sa, loA, hiA);
            float crossA = __fadd_rn(loA, hiA);
            float ttA    = __fadd_rn(s1A, s2c);
            float scoreA = __fmaf_rn(-2.0f, crossA, ttA);
            if (scoreA < bestA) { bestA = scoreA; idxA = t * TILE_C + c; }

            unsigned long long sb = add2(add2(B0, B1), add2(B2, B3));
            float loB, hiB; unpack2(sb, loB, hiB);
            float crossB = __fadd_rn(loB, hiB);
            float ttB    = __fadd_rn(s1B, s2c);
            float scoreB = __fmaf_rn(-2.0f, crossB, ttB);
            if (scoreB < bestB) { bestB = scoreB; idxB = t * TILE_C + c; }
        }
    }
    g_best_idx[rowA] = idxA;
    g_best_idx[rowB] = idxB;
}

// ---------------------------------------------------------------------------
// Kernel 2: gather + straight-through output + fp64 partial sums of (z_q - z)^2
// out = RN( z + RN(z_q - z) )   -- exact reference elementwise chain
// 16 consecutive elements per thread; shfl-based deterministic reduction.
// ---------------------------------------------------------------------------
__global__ void __launch_bounds__(K2_THREADS)
vq_apply_kernel(const float* __restrict__ z, const float* __restrict__ cb,
                float* __restrict__ out)
{
    __shared__ double s_warp[K2_THREADS / 32];

    const int tid  = threadIdx.x;
    const int lane = tid & 31;
    const int wid  = tid >> 5;
    const long long base = ((long long)blockIdx.x * K2_THREADS + tid) * 16;

    const int b   = (int)(base >> 18);
    const int cch = (int)(base >> 12) & 63;
    const int h   = (int)(base >> 6) & 63;
    const int w   = (int)base & 63;          // multiple of 16; stays in row
    const int row0 = b * HW + h * 64 + w;

    double acc = 0.0;
    #pragma unroll
    for (int g = 0; g < 4; g++) {
        float4 zv = *(const float4*)(z + base + 4 * g);
        int4   iv = *(const int4*)(g_best_idx + row0 + 4 * g);

        float q0 = cb[iv.x * DIM + cch];
        float q1 = cb[iv.y * DIM + cch];
        float q2 = cb[iv.z * DIM + cch];
        float q3 = cb[iv.w * DIM + cch];

        float d0 = __fadd_rn(q0, -zv.x);
        float d1 = __fadd_rn(q1, -zv.y);
        float d2 = __fadd_rn(q2, -zv.z);
        float d3 = __fadd_rn(q3, -zv.w);

        float4 ov;
        ov.x = __fadd_rn(zv.x, d0);
        ov.y = __fadd_rn(zv.y, d1);
        ov.z = __fadd_rn(zv.z, d2);
        ov.w = __fadd_rn(zv.w, d3);
        *(float4*)(out + base + 4 * g) = ov;

        float sg = __fadd_rn(__fadd_rn(__fmul_rn(d0, d0), __fmul_rn(d1, d1)),
                             __fadd_rn(__fmul_rn(d2, d2), __fmul_rn(d3, d3)));
        acc += (double)sg;
    }

    // deterministic warp reduction (fixed shuffle order)
    #pragma unroll
    for (int off = 16; off > 0; off >>= 1)
        acc += __shfl_down_sync(0xffffffffu, acc, off);
    if (lane == 0) s_warp[wid] = acc;
    __syncthreads();
    if (wid == 0) {
        double v = s_warp[lane];
        #pragma unroll
        for (int off = 16; off > 0; off >>= 1)
            v += __shfl_down_sync(0xffffffffu, v, off);
        if (lane == 0) g_partials[blockIdx.x] = v;
    }
}

// ---------------------------------------------------------------------------
// Kernel 3: deterministic final reduction + loss
// vq_loss = m + 0.25*m  where m = mean((z_q - z)^2)
// ---------------------------------------------------------------------------
__global__ void __launch_bounds__(K2_BLOCKS)
vq_loss_kernel(float* __restrict__ out, long long loss_pos)
{
    __shared__ double s_buf[K2_BLOCKS];
    const int tid = threadIdx.x;
    s_buf[tid] = g_partials[tid];
    __syncthreads();
    #pragma unroll
    for (int s = K2_BLOCKS / 2; s > 0; s >>= 1) {
        if (tid < s) s_buf[tid] += s_buf[tid + s];
        __syncthreads();
    }
    if (tid == 0) {
        float m = (float)(s_buf[0] * (1.0 / (double)N_ELEMS));
        float v = __fadd_rn(m, __fmul_rn(0.25f, m));
        out[loss_pos] = v;
    }
}

// ---------------------------------------------------------------------------
extern "C" void kernel_launch(void* const* d_in, const int* in_sizes, int n_in,
                              void* d_out, int out_size)
{
    const float* z  = (const float*)d_in[0];   // [32, 64, 64, 64] fp32
    const float* cb = (const float*)d_in[1];   // [1024, 64] fp32
    float* out = (float*)d_out;                // [8388608 z_q_st] + [1 loss]

    vq_argmin_kernel<<<N_ROWS / 512, 256>>>(z, cb);   // 256 blocks, 2 rows/thread
    vq_apply_kernel<<<K2_BLOCKS, K2_THREADS>>>(z, cb, out);

    long long loss_pos = (long long)out_size - 1;
    if (loss_pos < N_ELEMS) loss_pos = N_ELEMS;  // defensive; expect 8388609
    vq_loss_kernel<<<1, K2_BLOCKS>>>(out, loss_pos);
}